// round 15
// baseline (speedup 1.0000x reference)
#include <cuda_runtime.h>
#include <math.h>
#include <stdint.h>

#define BB 2
#define SS 2048
#define DD 1024
#define HH 16
#define HDD 64
#define MR (BB*SS)   // 4096 rows

// Scratch (allocation-free rule: __device__ globals)
__device__ __align__(16) float    g_kv[MR * 2 * DD];   // kv proj out (tf32-rounded)
__device__ __align__(16) float    g_q [MR * DD];       // q  proj out (tf32-rounded)
__device__ __align__(16) float    g_av[MR * DD];       // attn out (B,H,S,HD), rounded
__device__ __align__(16) unsigned g_xc  [MR * DD];     // x     tf32 bits
__device__ __align__(16) unsigned g_yc  [MR * DD];     // y     tf32 bits
__device__ __align__(16) unsigned g_wkvc[DD * 2 * DD]; // W_kv  tf32 bits
__device__ __align__(16) unsigned g_wqc [DD * DD];     // W_q   tf32 bits
__device__ __align__(16) unsigned g_woc [DD * DD];     // W_o   tf32 bits

#define FULLMASK 0xffffffffu

__device__ __forceinline__ unsigned f2tf32(float f) {
    unsigned u;
    asm("cvt.rna.tf32.f32 %0, %1;" : "=r"(u) : "f"(f));
    return u;
}

__device__ __forceinline__ float ex2f(float x) {
    float y;
    asm("ex2.approx.f32 %0, %1;" : "=f"(y) : "f"(x));
    return y;
}

__device__ __forceinline__ void mma_tf32(float* d, const unsigned* a,
                                         unsigned b0, unsigned b1) {
    asm volatile(
        "mma.sync.aligned.m16n8k8.row.col.f32.tf32.tf32.f32 "
        "{%0,%1,%2,%3}, {%4,%5,%6,%7}, {%8,%9}, {%0,%1,%2,%3};\n"
        : "+f"(d[0]), "+f"(d[1]), "+f"(d[2]), "+f"(d[3])
        : "r"(a[0]), "r"(a[1]), "r"(a[2]), "r"(a[3]), "r"(b0), "r"(b1));
}

__device__ __forceinline__ void cp16(void* dst_smem, const void* src) {
    unsigned d = (unsigned)__cvta_generic_to_shared(dst_smem);
    asm volatile("cp.async.cg.shared.global [%0], [%1], 16;\n" :: "r"(d), "l"(src));
}
__device__ __forceinline__ void cp_commit() {
    asm volatile("cp.async.commit_group;\n");
}
template <int N> __device__ __forceinline__ void cp_wait() {
    asm volatile("cp.async.wait_group %0;\n" :: "n"(N));
}

// ---------------------------------------------------------------------------
// Single fused pre-round pass for all 5 tensors
// ---------------------------------------------------------------------------
#define N4_X   (MR * DD / 4)
#define N4_WKV (DD * 2 * DD / 4)
#define N4_W   (DD * DD / 4)
#define N4_TOT (2 * N4_X + N4_WKV + 2 * N4_W)

__global__ __launch_bounds__(256) void cvt_all_kernel(
    const float* __restrict__ x,   unsigned* __restrict__ xc,
    const float* __restrict__ y,   unsigned* __restrict__ yc,
    const float* __restrict__ wkv, unsigned* __restrict__ wkvc,
    const float* __restrict__ wq,  unsigned* __restrict__ wqc,
    const float* __restrict__ wo,  unsigned* __restrict__ woc)
{
    int i = blockIdx.x * 256 + threadIdx.x;
    const int E1 = N4_X, E2 = 2 * N4_X, E3 = E2 + N4_WKV, E4 = E3 + N4_W,
              E5 = E4 + N4_W;
    const float* s; unsigned* d; int j;
    if      (i < E1) { s = x;   d = xc;   j = i; }
    else if (i < E2) { s = y;   d = yc;   j = i - E1; }
    else if (i < E3) { s = wkv; d = wkvc; j = i - E2; }
    else if (i < E4) { s = wq;  d = wqc;  j = i - E3; }
    else if (i < E5) { s = wo;  d = woc;  j = i - E4; }
    else return;
    float4 v = *(const float4*)(s + 4 * (size_t)j);
    uint4 u = make_uint4(f2tf32(v.x), f2tf32(v.y), f2tf32(v.z), f2tf32(v.w));
    *(uint4*)(d + 4 * (size_t)j) = u;
}

// ---------------------------------------------------------------------------
// Tensor-core tf32 GEMM body, 2-stage cp.async.
// Block tile 256x128, 8 warps (4m x 2n), warp tile 64x64 (4 m-frags).
// Each B-fragment pair feeds FOUR MMAs -> 32 LDS : 32 MMAs per k-step
// (was 24:16). As stride 36, Bs stride 136 (both conflict-free).
// ---------------------------------------------------------------------------
#define TBM 256
#define TBN 128
#define TBK 32
#define ASTR 36
#define BSTR 136
#define ABUF (TBM * ASTR)   // 9216 words
#define BBUF (TBK * BSTR)   // 4352 words
#define NGSTAGE 2
#define GEMM_SMEM (NGSTAGE * (ABUF + BBUF) * 4)  // 108544 bytes

template <int ROUND>
__device__ __forceinline__ void gemm_body(
    const unsigned* __restrict__ A, const unsigned* __restrict__ Bm,
    const float* __restrict__ bias, float* __restrict__ C,
    int M, int N, int K, int bx, int by, unsigned* smg)
{
    unsigned* As = smg;                      // [NGSTAGE][ABUF]
    unsigned* Bs = smg + NGSTAGE * ABUF;     // [NGSTAGE][BBUF]

    const int tid  = threadIdx.x;
    const int w    = tid >> 5;
    const int lane = tid & 31;
    const int g    = lane >> 2;
    const int t    = lane & 3;
    const int wm   = (w & 3) * 64;    // warp m-offset (4 warps in m)
    const int wn   = (w >> 2) * 64;   // warp n-offset (2 warps in n)
    const int brow = by * TBM;
    const int bcol = bx * TBN;

    float acc[4][8][4];
    #pragma unroll
    for (int mt = 0; mt < 4; mt++)
        #pragma unroll
        for (int nt = 0; nt < 8; nt++)
            #pragma unroll
            for (int j = 0; j < 4; j++) acc[mt][nt][j] = 0.f;

    auto load_tile = [&](int k0, int buf) {
        #pragma unroll
        for (int it = 0; it < 8; it++) {
            int i  = it * 256 + tid;
            int m  = i >> 3;
            int c4 = (i & 7) * 4;
            cp16(&As[buf * ABUF + m * ASTR + c4],
                 A + (size_t)(brow + m) * K + k0 + c4);
        }
        #pragma unroll
        for (int it = 0; it < 4; it++) {
            int i  = it * 256 + tid;
            int kk = i >> 5;
            int c4 = (i & 31) * 4;
            cp16(&Bs[buf * BBUF + kk * BSTR + c4],
                 Bm + (size_t)(k0 + kk) * N + bcol + c4);
        }
        cp_commit();
    };

    load_tile(0, 0);
    int buf = 0;
    for (int k0 = 0; k0 < K; k0 += TBK, buf ^= 1) {
        if (k0 + TBK < K) { load_tile(k0 + TBK, buf ^ 1); cp_wait<1>(); }
        else              { cp_wait<0>(); }
        __syncthreads();

        const unsigned* Ab = &As[buf * ABUF];
        const unsigned* Bb = &Bs[buf * BBUF];
        #pragma unroll
        for (int ks = 0; ks < TBK / 8; ks++) {
            unsigned af[4][4];
            #pragma unroll
            for (int mt = 0; mt < 4; mt++) {
                const unsigned* ab = &Ab[(wm + mt * 16) * ASTR + ks * 8];
                af[mt][0] = ab[g * ASTR + t];
                af[mt][1] = ab[(g + 8) * ASTR + t];
                af[mt][2] = ab[g * ASTR + t + 4];
                af[mt][3] = ab[(g + 8) * ASTR + t + 4];
            }
            const unsigned* bb0 = &Bb[(ks * 8 + t) * BSTR + wn + g];
            const unsigned* bb1 = &Bb[(ks * 8 + t + 4) * BSTR + wn + g];
            #pragma unroll
            for (int nt = 0; nt < 8; nt++) {
                unsigned b0 = bb0[nt * 8];
                unsigned b1 = bb1[nt * 8];
                mma_tf32(acc[0][nt], af[0], b0, b1);
                mma_tf32(acc[1][nt], af[1], b0, b1);
                mma_tf32(acc[2][nt], af[2], b0, b1);
                mma_tf32(acc[3][nt], af[3], b0, b1);
            }
        }
        __syncthreads();
    }

    // Epilogue: bias add (+ optional tf32 pre-round), coalesced float2 stores
    #pragma unroll
    for (int mt = 0; mt < 4; mt++) {
        const size_t r0 = (size_t)(brow + wm + mt * 16 + g);
        float* c0 = C + r0 * N;
        float* c1 = c0 + (size_t)8 * N;
        #pragma unroll
        for (int nt = 0; nt < 8; nt++) {
            int nc = bcol + wn + nt * 8 + 2 * t;
            float bx2 = bias[nc], by2 = bias[nc + 1];
            float v00 = acc[mt][nt][0] + bx2, v01 = acc[mt][nt][1] + by2;
            float v10 = acc[mt][nt][2] + bx2, v11 = acc[mt][nt][3] + by2;
            if (ROUND) {
                v00 = __uint_as_float(f2tf32(v00));
                v01 = __uint_as_float(f2tf32(v01));
                v10 = __uint_as_float(f2tf32(v10));
                v11 = __uint_as_float(f2tf32(v11));
            }
            *(float2*)&c0[nc] = make_float2(v00, v01);
            *(float2*)&c1[nc] = make_float2(v10, v11);
        }
    }
}

// Fused kv-proj + q-proj.
// kv: M=4096 (16 m-tiles of 256) x N=2048 (16 n-tiles) = 256 blocks.
// q:  16 m-tiles x 8 n-tiles = 128 blocks. Total 384.
__global__ __launch_bounds__(256) void proj_fused_kernel(
    const unsigned* __restrict__ xc, const unsigned* __restrict__ wkv,
    const float* __restrict__ bkv, float* __restrict__ kvp,
    const unsigned* __restrict__ yc, const unsigned* __restrict__ wq,
    const float* __restrict__ bq, float* __restrict__ qp)
{
    extern __shared__ unsigned smg[];
    int bid = blockIdx.x;
    if (bid < 256) {
        gemm_body<1>(xc, wkv, bkv, kvp, MR, 2 * DD, DD, bid & 15, bid >> 4, smg);
    } else {
        int r = bid - 256;
        gemm_body<1>(yc, wq, bq, qp, MR, DD, DD, r & 7, r >> 3, smg);
    }
}

// Plain single GEMM (o-projection, no rounding)
__global__ __launch_bounds__(256) void gemm_single_kernel(
    const unsigned* __restrict__ A, const unsigned* __restrict__ Bm,
    const float* __restrict__ bias, float* __restrict__ C,
    int M, int N, int K)
{
    extern __shared__ unsigned smg[];
    gemm_body<0>(A, Bm, bias, C, M, N, K, blockIdx.x, blockIdx.y, smg);
}

// ---------------------------------------------------------------------------
// Tensor-core flash attention (R14 winner, unchanged): 256 threads / 8 warps,
// 32 Q-rows per warp, shuffle-free P->A conversion via V row permutation,
// 3-stage cp.async, log2-domain softmax.
// ---------------------------------------------------------------------------
#define KSTRIDE 68
#define VSTRIDE 72
#define KBUF (64 * KSTRIDE)
#define VBUF (64 * VSTRIDE)
#define NASTAGE 3
#define ATTN_SMEM (NASTAGE * (KBUF + VBUF) * 4)

__global__ __launch_bounds__(256, 1) void attn_tc_kernel(
    const float* __restrict__ q, const float* __restrict__ kv,
    float* __restrict__ out)
{
    extern __shared__ unsigned sma[];
    unsigned* k_u = sma;
    unsigned* v_u = sma + NASTAGE * KBUF;

    const int tid  = threadIdx.x;
    const int w    = tid >> 5;
    const int lane = tid & 31;
    const int g    = lane >> 2;
    const int t    = lane & 3;
    const int bh   = blockIdx.y;
    const int b    = bh / HH;
    const int h    = bh % HH;
    const int q0   = blockIdx.x * 256;   // BQ=256: 8 warps x 32 rows

    const float* kvbase = kv + (size_t)b * SS * (2 * DD) + h * (2 * HDD);

    auto load_kv = [&](int kt, int buf) {
        #pragma unroll
        for (int it = 0; it < 4; it++) {
            int idx = it * 256 + tid;
            int row = idx >> 4;
            int c4  = (idx & 15) * 4;
            const float* src = kvbase + (size_t)(kt + row) * (2 * DD) + c4;
            cp16(&k_u[buf * KBUF + row * KSTRIDE + c4], src);
            int pos = row & 7;
            int rp  = (row & ~7) | ((pos & 1) ? (4 + (pos >> 1)) : (pos >> 1));
            cp16(&v_u[buf * VBUF + rp * VSTRIDE + c4], src + HDD);
        }
        cp_commit();
    };

    load_kv(0, 0);
    load_kv(64, 1);

    // Q fragments for both 16-row groups, scaled by 0.125*log2e
    const float QSCALE = 0.125f * 1.4426950408889634f;
    unsigned qa[2][8][4];
    #pragma unroll
    for (int mt = 0; mt < 2; mt++) {
        const float* q0p = q + (size_t)(b * SS + q0 + w * 32 + mt * 16 + g) * DD
                             + h * HDD;
        const float* q1p = q0p + (size_t)8 * DD;
        #pragma unroll
        for (int kj = 0; kj < 8; kj++) {
            qa[mt][kj][0] = __float_as_uint(q0p[8 * kj + t]     * QSCALE);
            qa[mt][kj][1] = __float_as_uint(q1p[8 * kj + t]     * QSCALE);
            qa[mt][kj][2] = __float_as_uint(q0p[8 * kj + t + 4] * QSCALE);
            qa[mt][kj][3] = __float_as_uint(q1p[8 * kj + t + 4] * QSCALE);
        }
    }

    float o[2][8][4];
    #pragma unroll
    for (int mt = 0; mt < 2; mt++)
        #pragma unroll
        for (int i = 0; i < 8; i++)
            #pragma unroll
            for (int j = 0; j < 4; j++) o[mt][i][j] = 0.f;
    float mH[2][2], lH[2][2];
    #pragma unroll
    for (int mt = 0; mt < 2; mt++) {
        mH[mt][0] = -INFINITY; mH[mt][1] = -INFINITY;
        lH[mt][0] = 0.f;       lH[mt][1] = 0.f;
    }

    const int ntiles = SS / 64;
    for (int i = 0; i < ntiles; i++) {
        if (i + 1 < ntiles) cp_wait<1>();
        else                cp_wait<0>();
        __syncthreads();
        if (i + 2 < ntiles) load_kv((i + 2) * 64, (i + 2) % NASTAGE);

        const unsigned* kb = &k_u[(i % NASTAGE) * KBUF];
        const unsigned* vb = &v_u[(i % NASTAGE) * VBUF];

        // S = Q @ K^T : each K b-frag feeds BOTH m-groups
        float s[2][8][4];
        #pragma unroll
        for (int nt = 0; nt < 8; nt++) {
            #pragma unroll
            for (int mt = 0; mt < 2; mt++)
                s[mt][nt][0] = s[mt][nt][1] = s[mt][nt][2] = s[mt][nt][3] = 0.f;
            const unsigned* krow = &kb[(8 * nt + g) * KSTRIDE];
            #pragma unroll
            for (int kj = 0; kj < 8; kj++) {
                unsigned b0 = krow[8 * kj + t];
                unsigned b1 = krow[8 * kj + t + 4];
                mma_tf32(s[0][nt], qa[0][kj], b0, b1);
                mma_tf32(s[1][nt], qa[1][kj], b0, b1);
            }
        }

        // Online softmax (log2 domain), per m-group — shuffle-free P frags
        unsigned pa[2][8][4];
        #pragma unroll
        for (int mt = 0; mt < 2; mt++) {
            float rmax0 = -INFINITY, rmax1 = -INFINITY;
            #pragma unroll
            for (int nt = 0; nt < 8; nt++) {
                rmax0 = fmaxf(rmax0, fmaxf(s[mt][nt][0], s[mt][nt][1]));
                rmax1 = fmaxf(rmax1, fmaxf(s[mt][nt][2], s[mt][nt][3]));
            }
            rmax0 = fmaxf(rmax0, __shfl_xor_sync(FULLMASK, rmax0, 1));
            rmax0 = fmaxf(rmax0, __shfl_xor_sync(FULLMASK, rmax0, 2));
            rmax1 = fmaxf(rmax1, __shfl_xor_sync(FULLMASK, rmax1, 1));
            rmax1 = fmaxf(rmax1, __shfl_xor_sync(FULLMASK, rmax1, 2));

            const float mn0 = fmaxf(mH[mt][0], rmax0);
            const float mn1 = fmaxf(mH[mt][1], rmax1);
            const float cr0 = ex2f(mH[mt][0] - mn0);
            const float cr1 = ex2f(mH[mt][1] - mn1);
            mH[mt][0] = mn0; mH[mt][1] = mn1;
            lH[mt][0] *= cr0; lH[mt][1] *= cr1;
            #pragma unroll
            for (int nt = 0; nt < 8; nt++) {
                o[mt][nt][0] *= cr0; o[mt][nt][1] *= cr0;
                o[mt][nt][2] *= cr1; o[mt][nt][3] *= cr1;
            }

            float ls0 = 0.f, ls1 = 0.f;
            #pragma unroll
            for (int nt = 0; nt < 8; nt++) {
                float p0 = ex2f(s[mt][nt][0] - mn0);
                float p1 = ex2f(s[mt][nt][1] - mn0);
                float p2 = ex2f(s[mt][nt][2] - mn1);
                float p3 = ex2f(s[mt][nt][3] - mn1);
                ls0 += p0 + p1; ls1 += p2 + p3;
                pa[mt][nt][0] = f2tf32(p0);
                pa[mt][nt][1] = f2tf32(p2);
                pa[mt][nt][2] = f2tf32(p1);
                pa[mt][nt][3] = f2tf32(p3);
            }
            ls0 += __shfl_xor_sync(FULLMASK, ls0, 1);
            ls0 += __shfl_xor_sync(FULLMASK, ls0, 2);
            ls1 += __shfl_xor_sync(FULLMASK, ls1, 1);
            ls1 += __shfl_xor_sync(FULLMASK, ls1, 2);
            lH[mt][0] += ls0; lH[mt][1] += ls1;
        }

        // O += P @ V : V rows permuted in smem to match sigma
        #pragma unroll
        for (int nd = 0; nd < 8; nd++) {
            #pragma unroll
            for (int kj = 0; kj < 8; kj++) {
                unsigned b0 = vb[(8 * kj + t)     * VSTRIDE + 8 * nd + g];
                unsigned b1 = vb[(8 * kj + t + 4) * VSTRIDE + 8 * nd + g];
                mma_tf32(o[0][nd], pa[0][kj], b0, b1);
                mma_tf32(o[1][nd], pa[1][kj], b0, b1);
            }
        }
    }

    // normalize + pre-round + store in (B,H,S,HD) layout
    #pragma unroll
    for (int mt = 0; mt < 2; mt++) {
        const float inv0 = 1.f / lH[mt][0];
        const float inv1 = 1.f / lH[mt][1];
        const size_t r0 = (size_t)(b * HH + h) * SS + q0 + w * 32 + mt * 16 + g;
        float* o0 = out + r0 * HDD;
        float* o1 = o0 + (size_t)8 * HDD;
        #pragma unroll
        for (int nt = 0; nt < 8; nt++) {
            int col = 8 * nt + 2 * t;
            float2 t0 = make_float2(__uint_as_float(f2tf32(o[mt][nt][0] * inv0)),
                                    __uint_as_float(f2tf32(o[mt][nt][1] * inv0)));
            float2 t1 = make_float2(__uint_as_float(f2tf32(o[mt][nt][2] * inv1)),
                                    __uint_as_float(f2tf32(o[mt][nt][3] * inv1)));
            *(float2*)&o0[col] = t0;
            *(float2*)&o1[col] = t1;
        }
    }
}

// ---------------------------------------------------------------------------
extern "C" void kernel_launch(void* const* d_in, const int* in_sizes, int n_in,
                              void* d_out, int out_size)
{
    const float* x    = (const float*)d_in[0];
    const float* y    = (const float*)d_in[1];
    const float* W_kv = (const float*)d_in[2];
    const float* b_kv = (const float*)d_in[3];
    const float* W_q  = (const float*)d_in[4];
    const float* b_q  = (const float*)d_in[5];
    const float* W_o  = (const float*)d_in[6];
    const float* b_o  = (const float*)d_in[7];
    float* out = (float*)d_out;

    float *kvp, *qp, *avp;
    unsigned *xc, *yc, *wkvc, *wqc, *woc;
    cudaGetSymbolAddress((void**)&kvp,  g_kv);
    cudaGetSymbolAddress((void**)&qp,   g_q);
    cudaGetSymbolAddress((void**)&avp,  g_av);
    cudaGetSymbolAddress((void**)&xc,   g_xc);
    cudaGetSymbolAddress((void**)&yc,   g_yc);
    cudaGetSymbolAddress((void**)&wkvc, g_wkvc);
    cudaGetSymbolAddress((void**)&wqc,  g_wqc);
    cudaGetSymbolAddress((void**)&woc,  g_woc);

    cudaFuncSetAttribute(proj_fused_kernel,
        cudaFuncAttributeMaxDynamicSharedMemorySize, GEMM_SMEM);
    cudaFuncSetAttribute(gemm_single_kernel,
        cudaFuncAttributeMaxDynamicSharedMemorySize, GEMM_SMEM);
    cudaFuncSetAttribute(attn_tc_kernel,
        cudaFuncAttributeMaxDynamicSharedMemorySize, ATTN_SMEM);

    // Single fused pre-round pass for all 5 tensors
    cvt_all_kernel<<<(N4_TOT + 255) / 256, 256>>>(
        x, xc, y, yc, W_kv, wkvc, W_q, wqc, W_o, woc);

    // Fused kv-proj + q-proj (384 blocks of 256x128 tiles), pre-rounded
    proj_fused_kernel<<<384, 256, GEMM_SMEM>>>(
        xc, wkvc, b_kv, kvp, yc, wqc, b_q, qp);

    // fused tensor-core attention (256 threads, 32 rows/warp) -> g_av
    attn_tc_kernel<<<dim3(SS / 256, BB * HH), 256, ATTN_SMEM>>>(
        qp, kvp, avp);

    // out = values @ W_o + b_o [4096 x 1024] (16 m-tiles x 8 n-tiles)
    gemm_single_kernel<<<dim3(DD / TBN, MR / TBM), 256, GEMM_SMEM>>>(
        (const unsigned*)avp, woc, b_o, out, MR, DD, DD);
}

// round 16
// speedup vs baseline: 1.0069x; 1.0069x over previous
#include <cuda_runtime.h>
#include <math.h>
#include <stdint.h>

#define BB 2
#define SS 2048
#define DD 1024
#define HH 16
#define HDD 64
#define MR (BB*SS)   // 4096 rows

// Scratch (allocation-free rule: __device__ globals)
__device__ __align__(16) float    g_kv[MR * 2 * DD];   // kv proj out (tf32-rounded)
__device__ __align__(16) float    g_q [MR * DD];       // q  proj out (tf32-rounded)
__device__ __align__(16) float    g_av[MR * DD];       // attn out (B,H,S,HD), rounded
__device__ __align__(16) unsigned g_xc  [MR * DD];     // x     tf32 bits
__device__ __align__(16) unsigned g_yc  [MR * DD];     // y     tf32 bits
__device__ __align__(16) unsigned g_wkvc[DD * 2 * DD]; // W_kv  tf32 bits
__device__ __align__(16) unsigned g_wqc [DD * DD];     // W_q   tf32 bits
__device__ __align__(16) unsigned g_woc [DD * DD];     // W_o   tf32 bits

#define FULLMASK 0xffffffffu

__device__ __forceinline__ unsigned f2tf32(float f) {
    unsigned u;
    asm("cvt.rna.tf32.f32 %0, %1;" : "=r"(u) : "f"(f));
    return u;
}

__device__ __forceinline__ float ex2f(float x) {
    float y;
    asm("ex2.approx.f32 %0, %1;" : "=f"(y) : "f"(x));
    return y;
}

__device__ __forceinline__ void mma_tf32(float* d, const unsigned* a,
                                         unsigned b0, unsigned b1) {
    asm volatile(
        "mma.sync.aligned.m16n8k8.row.col.f32.tf32.tf32.f32 "
        "{%0,%1,%2,%3}, {%4,%5,%6,%7}, {%8,%9}, {%0,%1,%2,%3};\n"
        : "+f"(d[0]), "+f"(d[1]), "+f"(d[2]), "+f"(d[3])
        : "r"(a[0]), "r"(a[1]), "r"(a[2]), "r"(a[3]), "r"(b0), "r"(b1));
}

__device__ __forceinline__ void cp16(void* dst_smem, const void* src) {
    unsigned d = (unsigned)__cvta_generic_to_shared(dst_smem);
    asm volatile("cp.async.cg.shared.global [%0], [%1], 16;\n" :: "r"(d), "l"(src));
}
__device__ __forceinline__ void cp_commit() {
    asm volatile("cp.async.commit_group;\n");
}
template <int N> __device__ __forceinline__ void cp_wait() {
    asm volatile("cp.async.wait_group %0;\n" :: "n"(N));
}

// ---------------------------------------------------------------------------
// Single fused pre-round pass for all 5 tensors
// ---------------------------------------------------------------------------
#define N4_X   (MR * DD / 4)
#define N4_WKV (DD * 2 * DD / 4)
#define N4_W   (DD * DD / 4)
#define N4_TOT (2 * N4_X + N4_WKV + 2 * N4_W)

__global__ __launch_bounds__(256) void cvt_all_kernel(
    const float* __restrict__ x,   unsigned* __restrict__ xc,
    const float* __restrict__ y,   unsigned* __restrict__ yc,
    const float* __restrict__ wkv, unsigned* __restrict__ wkvc,
    const float* __restrict__ wq,  unsigned* __restrict__ wqc,
    const float* __restrict__ wo,  unsigned* __restrict__ woc)
{
    int i = blockIdx.x * 256 + threadIdx.x;
    const int E1 = N4_X, E2 = 2 * N4_X, E3 = E2 + N4_WKV, E4 = E3 + N4_W,
              E5 = E4 + N4_W;
    const float* s; unsigned* d; int j;
    if      (i < E1) { s = x;   d = xc;   j = i; }
    else if (i < E2) { s = y;   d = yc;   j = i - E1; }
    else if (i < E3) { s = wkv; d = wkvc; j = i - E2; }
    else if (i < E4) { s = wq;  d = wqc;  j = i - E3; }
    else if (i < E5) { s = wo;  d = woc;  j = i - E4; }
    else return;
    float4 v = *(const float4*)(s + 4 * (size_t)j);
    uint4 u = make_uint4(f2tf32(v.x), f2tf32(v.y), f2tf32(v.z), f2tf32(v.w));
    *(uint4*)(d + 4 * (size_t)j) = u;
}

// ---------------------------------------------------------------------------
// Tensor-core tf32 GEMM body, 2-stage cp.async (R14 tile config) with
// SOFTWARE-PIPELINED fragment loads: k-step ks+1's LDS issue before ks's
// MMAs, so LDS latency retires under MMA execution (only ks=0 per tile
// exposes the 29-cyc LDS latency).
// ---------------------------------------------------------------------------
#define TBM 128
#define TBN 128
#define TBK 32
#define ASTR 36
#define BSTR 136
#define ABUF (TBM * ASTR)   // 4608 words
#define BBUF (TBK * BSTR)   // 4352 words
#define NGSTAGE 2
#define GEMM_SMEM (NGSTAGE * (ABUF + BBUF) * 4)  // 71680 bytes

template <int ROUND>
__device__ __forceinline__ void gemm_body(
    const unsigned* __restrict__ A, const unsigned* __restrict__ Bm,
    const float* __restrict__ bias, float* __restrict__ C,
    int M, int N, int K, int bx, int by, unsigned* smg)
{
    unsigned* As = smg;                      // [NGSTAGE][ABUF]
    unsigned* Bs = smg + NGSTAGE * ABUF;     // [NGSTAGE][BBUF]

    const int tid  = threadIdx.x;
    const int w    = tid >> 5;
    const int lane = tid & 31;
    const int g    = lane >> 2;
    const int t    = lane & 3;
    const int wm   = (w & 3) * 32;
    const int wn   = (w >> 2) * 64;
    const int brow = by * TBM;
    const int bcol = bx * TBN;

    float acc[2][8][4];
    #pragma unroll
    for (int mt = 0; mt < 2; mt++)
        #pragma unroll
        for (int nt = 0; nt < 8; nt++)
            #pragma unroll
            for (int j = 0; j < 4; j++) acc[mt][nt][j] = 0.f;

    auto load_tile = [&](int k0, int buf) {
        #pragma unroll
        for (int it = 0; it < 4; it++) {
            int i  = it * 256 + tid;
            int m  = i >> 3;
            int c4 = (i & 7) * 4;
            cp16(&As[buf * ABUF + m * ASTR + c4],
                 A + (size_t)(brow + m) * K + k0 + c4);
        }
        #pragma unroll
        for (int it = 0; it < 4; it++) {
            int i  = it * 256 + tid;
            int kk = i >> 5;
            int c4 = (i & 31) * 4;
            cp16(&Bs[buf * BBUF + kk * BSTR + c4],
                 Bm + (size_t)(k0 + kk) * N + bcol + c4);
        }
        cp_commit();
    };

    // fragment loaders (per k-step)
    auto load_afrag = [&](const unsigned* Ab, int ks, unsigned af[2][4]) {
        #pragma unroll
        for (int mt = 0; mt < 2; mt++) {
            const unsigned* ab = &Ab[(wm + mt * 16) * ASTR + ks * 8];
            af[mt][0] = ab[g * ASTR + t];
            af[mt][1] = ab[(g + 8) * ASTR + t];
            af[mt][2] = ab[g * ASTR + t + 4];
            af[mt][3] = ab[(g + 8) * ASTR + t + 4];
        }
    };
    auto load_bfrag = [&](const unsigned* Bb, int ks, unsigned bf0[8],
                          unsigned bf1[8]) {
        const unsigned* bb0 = &Bb[(ks * 8 + t) * BSTR + wn + g];
        const unsigned* bb1 = &Bb[(ks * 8 + t + 4) * BSTR + wn + g];
        #pragma unroll
        for (int nt = 0; nt < 8; nt++) {
            bf0[nt] = bb0[nt * 8];
            bf1[nt] = bb1[nt * 8];
        }
    };

    load_tile(0, 0);
    int buf = 0;
    for (int k0 = 0; k0 < K; k0 += TBK, buf ^= 1) {
        if (k0 + TBK < K) { load_tile(k0 + TBK, buf ^ 1); cp_wait<1>(); }
        else              { cp_wait<0>(); }
        __syncthreads();

        const unsigned* Ab = &As[buf * ABUF];
        const unsigned* Bb = &Bs[buf * BBUF];

        // software-pipelined fragments: double-buffered registers
        unsigned af[2][2][4], bf0[2][8], bf1[2][8];
        load_afrag(Ab, 0, af[0]);
        load_bfrag(Ab ? Bb : Bb, 0, bf0[0], bf1[0]);

        #pragma unroll
        for (int ks = 0; ks < TBK / 8; ks++) {
            const int cur = ks & 1;
            if (ks + 1 < TBK / 8) {
                load_afrag(Ab, ks + 1, af[cur ^ 1]);
                load_bfrag(Bb, ks + 1, bf0[cur ^ 1], bf1[cur ^ 1]);
            }
            #pragma unroll
            for (int nt = 0; nt < 8; nt++) {
                mma_tf32(acc[0][nt], af[cur][0], bf0[cur][nt], bf1[cur][nt]);
                mma_tf32(acc[1][nt], af[cur][1], bf0[cur][nt], bf1[cur][nt]);
            }
        }
        __syncthreads();
    }

    // Epilogue: bias add (+ optional tf32 pre-round), coalesced float2 stores
    #pragma unroll
    for (int mt = 0; mt < 2; mt++) {
        const size_t r0 = (size_t)(brow + wm + mt * 16 + g);
        float* c0 = C + r0 * N;
        float* c1 = c0 + (size_t)8 * N;
        #pragma unroll
        for (int nt = 0; nt < 8; nt++) {
            int nc = bcol + wn + nt * 8 + 2 * t;
            float bx2 = bias[nc], by2 = bias[nc + 1];
            float v00 = acc[mt][nt][0] + bx2, v01 = acc[mt][nt][1] + by2;
            float v10 = acc[mt][nt][2] + bx2, v11 = acc[mt][nt][3] + by2;
            if (ROUND) {
                v00 = __uint_as_float(f2tf32(v00));
                v01 = __uint_as_float(f2tf32(v01));
                v10 = __uint_as_float(f2tf32(v10));
                v11 = __uint_as_float(f2tf32(v11));
            }
            *(float2*)&c0[nc] = make_float2(v00, v01);
            *(float2*)&c1[nc] = make_float2(v10, v11);
        }
    }
}

// Fused kv-proj + q-proj: blocks [0,512) do kv (N=2048), [512,768) do q.
__global__ __launch_bounds__(256) void proj_fused_kernel(
    const unsigned* __restrict__ xc, const unsigned* __restrict__ wkv,
    const float* __restrict__ bkv, float* __restrict__ kvp,
    const unsigned* __restrict__ yc, const unsigned* __restrict__ wq,
    const float* __restrict__ bq, float* __restrict__ qp)
{
    extern __shared__ unsigned smg[];
    int bid = blockIdx.x;
    if (bid < 512) {
        gemm_body<1>(xc, wkv, bkv, kvp, MR, 2 * DD, DD, bid & 15, bid >> 4, smg);
    } else {
        int r = bid - 512;
        gemm_body<1>(yc, wq, bq, qp, MR, DD, DD, r & 7, r >> 3, smg);
    }
}

// Plain single GEMM (o-projection, no rounding)
__global__ __launch_bounds__(256) void gemm_single_kernel(
    const unsigned* __restrict__ A, const unsigned* __restrict__ Bm,
    const float* __restrict__ bias, float* __restrict__ C,
    int M, int N, int K)
{
    extern __shared__ unsigned smg[];
    gemm_body<0>(A, Bm, bias, C, M, N, K, blockIdx.x, blockIdx.y, smg);
}

// ---------------------------------------------------------------------------
// Tensor-core flash attention (R14 winner, unchanged): 256 threads / 8 warps,
// 32 Q-rows per warp, shuffle-free P->A conversion via V row permutation,
// 3-stage cp.async, log2-domain softmax.
// ---------------------------------------------------------------------------
#define KSTRIDE 68
#define VSTRIDE 72
#define KBUF (64 * KSTRIDE)
#define VBUF (64 * VSTRIDE)
#define NASTAGE 3
#define ATTN_SMEM (NASTAGE * (KBUF + VBUF) * 4)

__global__ __launch_bounds__(256, 1) void attn_tc_kernel(
    const float* __restrict__ q, const float* __restrict__ kv,
    float* __restrict__ out)
{
    extern __shared__ unsigned sma[];
    unsigned* k_u = sma;
    unsigned* v_u = sma + NASTAGE * KBUF;

    const int tid  = threadIdx.x;
    const int w    = tid >> 5;
    const int lane = tid & 31;
    const int g    = lane >> 2;
    const int t    = lane & 3;
    const int bh   = blockIdx.y;
    const int b    = bh / HH;
    const int h    = bh % HH;
    const int q0   = blockIdx.x * 256;   // BQ=256: 8 warps x 32 rows

    const float* kvbase = kv + (size_t)b * SS * (2 * DD) + h * (2 * HDD);

    auto load_kv = [&](int kt, int buf) {
        #pragma unroll
        for (int it = 0; it < 4; it++) {
            int idx = it * 256 + tid;
            int row = idx >> 4;
            int c4  = (idx & 15) * 4;
            const float* src = kvbase + (size_t)(kt + row) * (2 * DD) + c4;
            cp16(&k_u[buf * KBUF + row * KSTRIDE + c4], src);
            int pos = row & 7;
            int rp  = (row & ~7) | ((pos & 1) ? (4 + (pos >> 1)) : (pos >> 1));
            cp16(&v_u[buf * VBUF + rp * VSTRIDE + c4], src + HDD);
        }
        cp_commit();
    };

    load_kv(0, 0);
    load_kv(64, 1);

    // Q fragments for both 16-row groups, scaled by 0.125*log2e
    const float QSCALE = 0.125f * 1.4426950408889634f;
    unsigned qa[2][8][4];
    #pragma unroll
    for (int mt = 0; mt < 2; mt++) {
        const float* q0p = q + (size_t)(b * SS + q0 + w * 32 + mt * 16 + g) * DD
                             + h * HDD;
        const float* q1p = q0p + (size_t)8 * DD;
        #pragma unroll
        for (int kj = 0; kj < 8; kj++) {
            qa[mt][kj][0] = __float_as_uint(q0p[8 * kj + t]     * QSCALE);
            qa[mt][kj][1] = __float_as_uint(q1p[8 * kj + t]     * QSCALE);
            qa[mt][kj][2] = __float_as_uint(q0p[8 * kj + t + 4] * QSCALE);
            qa[mt][kj][3] = __float_as_uint(q1p[8 * kj + t + 4] * QSCALE);
        }
    }

    float o[2][8][4];
    #pragma unroll
    for (int mt = 0; mt < 2; mt++)
        #pragma unroll
        for (int i = 0; i < 8; i++)
            #pragma unroll
            for (int j = 0; j < 4; j++) o[mt][i][j] = 0.f;
    float mH[2][2], lH[2][2];
    #pragma unroll
    for (int mt = 0; mt < 2; mt++) {
        mH[mt][0] = -INFINITY; mH[mt][1] = -INFINITY;
        lH[mt][0] = 0.f;       lH[mt][1] = 0.f;
    }

    const int ntiles = SS / 64;
    for (int i = 0; i < ntiles; i++) {
        if (i + 1 < ntiles) cp_wait<1>();
        else                cp_wait<0>();
        __syncthreads();
        if (i + 2 < ntiles) load_kv((i + 2) * 64, (i + 2) % NASTAGE);

        const unsigned* kb = &k_u[(i % NASTAGE) * KBUF];
        const unsigned* vb = &v_u[(i % NASTAGE) * VBUF];

        // S = Q @ K^T : each K b-frag feeds BOTH m-groups
        float s[2][8][4];
        #pragma unroll
        for (int nt = 0; nt < 8; nt++) {
            #pragma unroll
            for (int mt = 0; mt < 2; mt++)
                s[mt][nt][0] = s[mt][nt][1] = s[mt][nt][2] = s[mt][nt][3] = 0.f;
            const unsigned* krow = &kb[(8 * nt + g) * KSTRIDE];
            #pragma unroll
            for (int kj = 0; kj < 8; kj++) {
                unsigned b0 = krow[8 * kj + t];
                unsigned b1 = krow[8 * kj + t + 4];
                mma_tf32(s[0][nt], qa[0][kj], b0, b1);
                mma_tf32(s[1][nt], qa[1][kj], b0, b1);
            }
        }

        // Online softmax (log2 domain), per m-group — shuffle-free P frags
        unsigned pa[2][8][4];
        #pragma unroll
        for (int mt = 0; mt < 2; mt++) {
            float rmax0 = -INFINITY, rmax1 = -INFINITY;
            #pragma unroll
            for (int nt = 0; nt < 8; nt++) {
                rmax0 = fmaxf(rmax0, fmaxf(s[mt][nt][0], s[mt][nt][1]));
                rmax1 = fmaxf(rmax1, fmaxf(s[mt][nt][2], s[mt][nt][3]));
            }
            rmax0 = fmaxf(rmax0, __shfl_xor_sync(FULLMASK, rmax0, 1));
            rmax0 = fmaxf(rmax0, __shfl_xor_sync(FULLMASK, rmax0, 2));
            rmax1 = fmaxf(rmax1, __shfl_xor_sync(FULLMASK, rmax1, 1));
            rmax1 = fmaxf(rmax1, __shfl_xor_sync(FULLMASK, rmax1, 2));

            const float mn0 = fmaxf(mH[mt][0], rmax0);
            const float mn1 = fmaxf(mH[mt][1], rmax1);
            const float cr0 = ex2f(mH[mt][0] - mn0);
            const float cr1 = ex2f(mH[mt][1] - mn1);
            mH[mt][0] = mn0; mH[mt][1] = mn1;
            lH[mt][0] *= cr0; lH[mt][1] *= cr1;
            #pragma unroll
            for (int nt = 0; nt < 8; nt++) {
                o[mt][nt][0] *= cr0; o[mt][nt][1] *= cr0;
                o[mt][nt][2] *= cr1; o[mt][nt][3] *= cr1;
            }

            float ls0 = 0.f, ls1 = 0.f;
            #pragma unroll
            for (int nt = 0; nt < 8; nt++) {
                float p0 = ex2f(s[mt][nt][0] - mn0);
                float p1 = ex2f(s[mt][nt][1] - mn0);
                float p2 = ex2f(s[mt][nt][2] - mn1);
                float p3 = ex2f(s[mt][nt][3] - mn1);
                ls0 += p0 + p1; ls1 += p2 + p3;
                pa[mt][nt][0] = f2tf32(p0);
                pa[mt][nt][1] = f2tf32(p2);
                pa[mt][nt][2] = f2tf32(p1);
                pa[mt][nt][3] = f2tf32(p3);
            }
            ls0 += __shfl_xor_sync(FULLMASK, ls0, 1);
            ls0 += __shfl_xor_sync(FULLMASK, ls0, 2);
            ls1 += __shfl_xor_sync(FULLMASK, ls1, 1);
            ls1 += __shfl_xor_sync(FULLMASK, ls1, 2);
            lH[mt][0] += ls0; lH[mt][1] += ls1;
        }

        // O += P @ V : V rows permuted in smem to match sigma
        #pragma unroll
        for (int nd = 0; nd < 8; nd++) {
            #pragma unroll
            for (int kj = 0; kj < 8; kj++) {
                unsigned b0 = vb[(8 * kj + t)     * VSTRIDE + 8 * nd + g];
                unsigned b1 = vb[(8 * kj + t + 4) * VSTRIDE + 8 * nd + g];
                mma_tf32(o[0][nd], pa[0][kj], b0, b1);
                mma_tf32(o[1][nd], pa[1][kj], b0, b1);
            }
        }
    }

    // normalize + pre-round + store in (B,H,S,HD) layout
    #pragma unroll
    for (int mt = 0; mt < 2; mt++) {
        const float inv0 = 1.f / lH[mt][0];
        const float inv1 = 1.f / lH[mt][1];
        const size_t r0 = (size_t)(b * HH + h) * SS + q0 + w * 32 + mt * 16 + g;
        float* o0 = out + r0 * HDD;
        float* o1 = o0 + (size_t)8 * HDD;
        #pragma unroll
        for (int nt = 0; nt < 8; nt++) {
            int col = 8 * nt + 2 * t;
            float2 t0 = make_float2(__uint_as_float(f2tf32(o[mt][nt][0] * inv0)),
                                    __uint_as_float(f2tf32(o[mt][nt][1] * inv0)));
            float2 t1 = make_float2(__uint_as_float(f2tf32(o[mt][nt][2] * inv1)),
                                    __uint_as_float(f2tf32(o[mt][nt][3] * inv1)));
            *(float2*)&o0[col] = t0;
            *(float2*)&o1[col] = t1;
        }
    }
}

// ---------------------------------------------------------------------------
extern "C" void kernel_launch(void* const* d_in, const int* in_sizes, int n_in,
                              void* d_out, int out_size)
{
    const float* x    = (const float*)d_in[0];
    const float* y    = (const float*)d_in[1];
    const float* W_kv = (const float*)d_in[2];
    const float* b_kv = (const float*)d_in[3];
    const float* W_q  = (const float*)d_in[4];
    const float* b_q  = (const float*)d_in[5];
    const float* W_o  = (const float*)d_in[6];
    const float* b_o  = (const float*)d_in[7];
    float* out = (float*)d_out;

    float *kvp, *qp, *avp;
    unsigned *xc, *yc, *wkvc, *wqc, *woc;
    cudaGetSymbolAddress((void**)&kvp,  g_kv);
    cudaGetSymbolAddress((void**)&qp,   g_q);
    cudaGetSymbolAddress((void**)&avp,  g_av);
    cudaGetSymbolAddress((void**)&xc,   g_xc);
    cudaGetSymbolAddress((void**)&yc,   g_yc);
    cudaGetSymbolAddress((void**)&wkvc, g_wkvc);
    cudaGetSymbolAddress((void**)&wqc,  g_wqc);
    cudaGetSymbolAddress((void**)&woc,  g_woc);

    cudaFuncSetAttribute(proj_fused_kernel,
        cudaFuncAttributeMaxDynamicSharedMemorySize, GEMM_SMEM);
    cudaFuncSetAttribute(gemm_single_kernel,
        cudaFuncAttributeMaxDynamicSharedMemorySize, GEMM_SMEM);
    cudaFuncSetAttribute(attn_tc_kernel,
        cudaFuncAttributeMaxDynamicSharedMemorySize, ATTN_SMEM);

    // Single fused pre-round pass for all 5 tensors
    cvt_all_kernel<<<(N4_TOT + 255) / 256, 256>>>(
        x, xc, y, yc, W_kv, wkvc, W_q, wqc, W_o, woc);

    // Fused kv-proj + q-proj (768 blocks), outputs pre-rounded
    proj_fused_kernel<<<768, 256, GEMM_SMEM>>>(
        xc, wkvc, b_kv, kvp, yc, wqc, b_q, qp);

    // fused tensor-core attention (256 threads, 32 rows/warp) -> g_av
    attn_tc_kernel<<<dim3(SS / 256, BB * HH), 256, ATTN_SMEM>>>(
        qp, kvp, avp);

    // out = values @ W_o + b_o [4096 x 1024]
    gemm_single_kernel<<<dim3(DD / TBN, MR / TBM), 256, GEMM_SMEM>>>(
        (const unsigned*)avp, woc, b_o, out, MR, DD, DD);
}

// round 17
// speedup vs baseline: 1.7604x; 1.7484x over previous
#include <cuda_runtime.h>
#include <cuda_fp16.h>
#include <math.h>
#include <stdint.h>

#define BB 2
#define SS 2048
#define DD 1024
#define HH 16
#define HDD 64
#define MR (BB*SS)   // 4096 rows

// Scratch (allocation-free rule: __device__ globals)
__device__ __align__(16) __half   g_kvh[MR * 2 * DD];      // kv out, fp16
__device__ __align__(16) __half   g_qh [MR * DD];          // q out, fp16
__device__ __align__(16) __half   g_avh[MR * DD];          // attn out (B,H,S,HD), fp16
__device__ __align__(16) __half   g_xh [MR * DD];          // x fp16
__device__ __align__(16) __half   g_yh [MR * DD];          // y fp16
__device__ __align__(16) unsigned g_wkvh[(DD/2) * 2 * DD]; // W_kv k-pair words
__device__ __align__(16) unsigned g_wqh [(DD/2) * DD];     // W_q  k-pair words
__device__ __align__(16) unsigned g_woh [(DD/2) * DD];     // W_o  k-pair words

#define FULLMASK 0xffffffffu

__device__ __forceinline__ unsigned pack2h(float lo, float hi) {
    __half2 h = __floats2half2_rn(lo, hi);   // lo -> .x (low half)
    return *(unsigned*)&h;
}

__device__ __forceinline__ float ex2f(float x) {
    float y;
    asm("ex2.approx.f32 %0, %1;" : "=f"(y) : "f"(x));
    return y;
}

// fp16 MMA m16n8k16, fp32 accumulate
__device__ __forceinline__ void mma_f16(float* d, const unsigned* a,
                                        unsigned b0, unsigned b1) {
    asm volatile(
        "mma.sync.aligned.m16n8k16.row.col.f32.f16.f16.f32 "
        "{%0,%1,%2,%3}, {%4,%5,%6,%7}, {%8,%9}, {%0,%1,%2,%3};\n"
        : "+f"(d[0]), "+f"(d[1]), "+f"(d[2]), "+f"(d[3])
        : "r"(a[0]), "r"(a[1]), "r"(a[2]), "r"(a[3]), "r"(b0), "r"(b1));
}

__device__ __forceinline__ void ldm_x2_trans(unsigned& r0, unsigned& r1,
                                             unsigned addr) {
    asm volatile(
        "ldmatrix.sync.aligned.m8n8.x2.trans.shared.b16 {%0,%1}, [%2];"
        : "=r"(r0), "=r"(r1) : "r"(addr));
}

__device__ __forceinline__ void cp16(void* dst_smem, const void* src) {
    unsigned d = (unsigned)__cvta_generic_to_shared(dst_smem);
    asm volatile("cp.async.cg.shared.global [%0], [%1], 16;\n" :: "r"(d), "l"(src));
}
__device__ __forceinline__ void cp_commit() {
    asm volatile("cp.async.commit_group;\n");
}
template <int N> __device__ __forceinline__ void cp_wait() {
    asm volatile("cp.async.wait_group %0;\n" :: "n"(N));
}

// ---------------------------------------------------------------------------
// cvt passes: fp32 -> fp16
// A-style (x,y): row-major halfs, same layout.
// B-style (weights): k-pair interleaved words  word[kp][n] = (W[2kp][n], W[2kp+1][n])
// ---------------------------------------------------------------------------
#define N4_X (MR * DD / 4)

__global__ __launch_bounds__(256) void cvtA_kernel(
    const float* __restrict__ x, __half* __restrict__ xh,
    const float* __restrict__ y, __half* __restrict__ yh)
{
    int i = blockIdx.x * 256 + threadIdx.x;
    const float* s; __half* d; int j;
    if (i < N4_X) { s = x; d = xh; j = i; }
    else if (i < 2 * N4_X) { s = y; d = yh; j = i - N4_X; }
    else return;
    float4 v = *(const float4*)(s + 4 * (size_t)j);
    unsigned* dw = (unsigned*)d;
    dw[2 * j]     = pack2h(v.x, v.y);
    dw[2 * j + 1] = pack2h(v.z, v.w);
}

#define NW_KV ((DD / 2) * 2 * DD)   // 1M words
#define NW_W  ((DD / 2) * DD)       // 512K words

__global__ __launch_bounds__(256) void cvtB_kernel(
    const float* __restrict__ wkv, unsigned* __restrict__ wkvh,
    const float* __restrict__ wq,  unsigned* __restrict__ wqh,
    const float* __restrict__ wo,  unsigned* __restrict__ woh)
{
    int i = blockIdx.x * 256 + threadIdx.x;
    if (i < NW_KV) {
        int kp = i >> 11, n = i & 2047;
        wkvh[i] = pack2h(wkv[(size_t)(2 * kp) * 2048 + n],
                         wkv[(size_t)(2 * kp + 1) * 2048 + n]);
    } else if (i < NW_KV + NW_W) {
        int j = i - NW_KV;
        int kp = j >> 10, n = j & 1023;
        wqh[j] = pack2h(wq[(size_t)(2 * kp) * 1024 + n],
                        wq[(size_t)(2 * kp + 1) * 1024 + n]);
    } else if (i < NW_KV + 2 * NW_W) {
        int j = i - NW_KV - NW_W;
        int kp = j >> 10, n = j & 1023;
        woh[j] = pack2h(wo[(size_t)(2 * kp) * 1024 + n],
                        wo[(size_t)(2 * kp + 1) * 1024 + n]);
    }
}

// ---------------------------------------------------------------------------
// fp16 tensor-core GEMM: C[M,N] = A[M,K] @ B[K,N] + bias.
// A: fp16 [M][K] row-major. B: k-pair word array [K/2][N].
// Block 128x128, TBK=32 (2 k-steps of 16), 8 warps (4m x 2n), warp 32x64.
// As halfs stride 72 (36 words/row): A-frag banks 4g+t, CF.
// Bs words [16][136]: B-frag banks 8t+g(+8nt), CF.
// OUTH=1: round to fp16 and store halfs; OUTH=0: fp32 out.
// ---------------------------------------------------------------------------
#define TBM 128
#define TBN 128
#define TBK 32
#define ASTRH 72                 // halfs per As row
#define ABUF_B (TBM * ASTRH * 2) // 18432 bytes
#define BSTRW 136                // words per Bs kp-row
#define BBUF_B (16 * BSTRW * 4)  // 8704 bytes
#define NGSTAGE 2
#define GEMM_SMEM (NGSTAGE * (ABUF_B + BBUF_B))  // 54272 bytes

template <int OUTH>
__device__ __forceinline__ void gemm_body(
    const __half* __restrict__ A, const unsigned* __restrict__ Bw,
    const float* __restrict__ bias, void* __restrict__ Cv,
    int M, int N, int K, int bx, int by, char* smc)
{
    __half*   As = (__half*)smc;                       // [NG][128][72]
    unsigned* Bs = (unsigned*)(smc + NGSTAGE * ABUF_B); // [NG][16][136]

    const int tid  = threadIdx.x;
    const int w    = tid >> 5;
    const int lane = tid & 31;
    const int g    = lane >> 2;
    const int t    = lane & 3;
    const int wm   = (w & 3) * 32;
    const int wn   = (w >> 2) * 64;
    const int brow = by * TBM;
    const int bcol = bx * TBN;

    float acc[2][8][4];
    #pragma unroll
    for (int mt = 0; mt < 2; mt++)
        #pragma unroll
        for (int nt = 0; nt < 8; nt++)
            #pragma unroll
            for (int j = 0; j < 4; j++) acc[mt][nt][j] = 0.f;

    auto load_tile = [&](int k0, int buf) {
        // A tile: 128 rows x 32 halfs (64B) = 512 cp16
        #pragma unroll
        for (int it = 0; it < 2; it++) {
            int i = it * 256 + tid;                 // 0..511
            int m = i >> 2;
            int c = (i & 3) * 8;                    // half offset
            cp16(As + (size_t)buf * (ABUF_B / 2) + m * ASTRH + c,
                 A + (size_t)(brow + m) * K + k0 + c);
        }
        // B tile: 16 kp-rows x 128 words (512B) = 512 cp16
        #pragma unroll
        for (int it = 0; it < 2; it++) {
            int i  = it * 256 + tid;
            int kp = i >> 5;
            int c4 = (i & 31) * 4;
            cp16(Bs + (size_t)buf * (BBUF_B / 4) + kp * BSTRW + c4,
                 Bw + (size_t)(k0 / 2 + kp) * N + bcol + c4);
        }
        cp_commit();
    };

    load_tile(0, 0);
    int buf = 0;
    for (int k0 = 0; k0 < K; k0 += TBK, buf ^= 1) {
        if (k0 + TBK < K) { load_tile(k0 + TBK, buf ^ 1); cp_wait<1>(); }
        else              { cp_wait<0>(); }
        __syncthreads();

        const unsigned* Aw = (const unsigned*)(As + (size_t)buf * (ABUF_B / 2));
        const unsigned* Bb = Bs + (size_t)buf * (BBUF_B / 4);
        #pragma unroll
        for (int ks = 0; ks < 2; ks++) {
            unsigned af[2][4];
            #pragma unroll
            for (int mt = 0; mt < 2; mt++) {
                const unsigned* ab = &Aw[(wm + mt * 16) * 36 + ks * 8];
                af[mt][0] = ab[g * 36 + t];           // (g,   k 2t..2t+1)
                af[mt][1] = ab[(g + 8) * 36 + t];     // (g+8, k 2t..2t+1)
                af[mt][2] = ab[g * 36 + t + 4];       // (g,   k 2t+8..)
                af[mt][3] = ab[(g + 8) * 36 + t + 4]; // (g+8, k 2t+8..)
            }
            const unsigned* bb0 = &Bb[(ks * 8 + t) * BSTRW + wn + g];
            const unsigned* bb1 = &Bb[(ks * 8 + t + 4) * BSTRW + wn + g];
            #pragma unroll
            for (int nt = 0; nt < 8; nt++) {
                unsigned b0 = bb0[nt * 8];
                unsigned b1 = bb1[nt * 8];
                mma_f16(acc[0][nt], af[0], b0, b1);
                mma_f16(acc[1][nt], af[1], b0, b1);
            }
        }
        __syncthreads();
    }

    // Epilogue
    #pragma unroll
    for (int mt = 0; mt < 2; mt++) {
        const size_t r0 = (size_t)(brow + wm + mt * 16 + g);
        #pragma unroll
        for (int nt = 0; nt < 8; nt++) {
            int nc = bcol + wn + nt * 8 + 2 * t;
            float bx2 = bias[nc], by2 = bias[nc + 1];
            float v00 = acc[mt][nt][0] + bx2, v01 = acc[mt][nt][1] + by2;
            float v10 = acc[mt][nt][2] + bx2, v11 = acc[mt][nt][3] + by2;
            if (OUTH) {
                __half* C = (__half*)Cv;
                *(unsigned*)&C[r0 * N + nc]             = pack2h(v00, v01);
                *(unsigned*)&C[(r0 + 8) * N + nc]       = pack2h(v10, v11);
            } else {
                float* C = (float*)Cv;
                *(float2*)&C[r0 * N + nc]       = make_float2(v00, v01);
                *(float2*)&C[(r0 + 8) * N + nc] = make_float2(v10, v11);
            }
        }
    }
}

// Fused kv-proj + q-proj: blocks [0,512) kv (N=2048), [512,768) q.
__global__ __launch_bounds__(256) void proj_fused_kernel(
    const __half* __restrict__ xh, const unsigned* __restrict__ wkvh,
    const float* __restrict__ bkv, __half* __restrict__ kvh,
    const __half* __restrict__ yh, const unsigned* __restrict__ wqh,
    const float* __restrict__ bq, __half* __restrict__ qh)
{
    extern __shared__ char smc[];
    int bid = blockIdx.x;
    if (bid < 512) {
        gemm_body<1>(xh, wkvh, bkv, kvh, MR, 2 * DD, DD, bid & 15, bid >> 4, smc);
    } else {
        int r = bid - 512;
        gemm_body<1>(yh, wqh, bq, qh, MR, DD, DD, r & 7, r >> 3, smc);
    }
}

// o-projection: fp32 output
__global__ __launch_bounds__(256) void gemm_single_kernel(
    const __half* __restrict__ A, const unsigned* __restrict__ Bw,
    const float* __restrict__ bias, float* __restrict__ C,
    int M, int N, int K)
{
    extern __shared__ char smc[];
    gemm_body<0>(A, Bw, bias, C, M, N, K, blockIdx.x, blockIdx.y, smc);
}

// ---------------------------------------------------------------------------
// fp16 tensor-core flash attention: 256 threads / 8 warps, 32 Q-rows/warp,
// m16n8k16. K tile [key][72 halfs] (scalar word b-frags, banks 4g+t);
// V tile [key][72 halfs], B-frags via ldmatrix.x2.trans (CF at 144B stride).
// P->A-frag is pure register packing (m16n8k16 A k-pairs == acc col pairs).
// 3-stage cp.async, log2-domain softmax (scale applied to S in fp32).
// ---------------------------------------------------------------------------
#define KSTRH 72
#define KBUF_B (64 * KSTRH * 2)   // 9216 bytes
#define VBUF_B (64 * KSTRH * 2)   // 9216 bytes
#define NASTAGE 3
#define ATTN_SMEM (NASTAGE * (KBUF_B + VBUF_B))  // 55296 bytes

__global__ __launch_bounds__(256, 1) void attn_tc_kernel(
    const __half* __restrict__ q, const __half* __restrict__ kv,
    __half* __restrict__ out)
{
    extern __shared__ char sma[];
    __half* k_s = (__half*)sma;                       // [NA][64][72]
    __half* v_s = (__half*)(sma + NASTAGE * KBUF_B);  // [NA][64][72]

    const int tid  = threadIdx.x;
    const int w    = tid >> 5;
    const int lane = tid & 31;
    const int g    = lane >> 2;
    const int t    = lane & 3;
    const int bh   = blockIdx.y;
    const int b    = bh / HH;
    const int h    = bh % HH;
    const int q0   = blockIdx.x * 256;   // BQ=256: 8 warps x 32 rows

    const __half* kvbase = kv + (size_t)b * SS * (2 * DD) + h * (2 * HDD);

    auto load_kv = [&](int kt, int buf) {
        #pragma unroll
        for (int it = 0; it < 2; it++) {              // K: 64 rows x 128B
            int idx = it * 256 + tid;
            int row = idx >> 3;
            int c   = (idx & 7) * 8;
            cp16(k_s + (size_t)buf * (KBUF_B / 2) + row * KSTRH + c,
                 kvbase + (size_t)(kt + row) * (2 * DD) + c);
        }
        #pragma unroll
        for (int it = 0; it < 2; it++) {              // V: 64 rows x 128B
            int idx = it * 256 + tid;
            int row = idx >> 3;
            int c   = (idx & 7) * 8;
            cp16(v_s + (size_t)buf * (VBUF_B / 2) + row * KSTRH + c,
                 kvbase + (size_t)(kt + row) * (2 * DD) + HDD + c);
        }
        cp_commit();
    };

    load_kv(0, 0);
    load_kv(64, 1);

    // Q fragments (fp16, unscaled; S scaled in fp32 after MMA)
    unsigned qa[2][4][4];
    #pragma unroll
    for (int mt = 0; mt < 2; mt++) {
        const unsigned* q0p = (const unsigned*)(
            q + (size_t)(b * SS + q0 + w * 32 + mt * 16 + g) * DD + h * HDD);
        const unsigned* q1p = (const unsigned*)(
            q + (size_t)(b * SS + q0 + w * 32 + mt * 16 + g + 8) * DD + h * HDD);
        #pragma unroll
        for (int kj = 0; kj < 4; kj++) {
            qa[mt][kj][0] = q0p[8 * kj + t];
            qa[mt][kj][1] = q1p[8 * kj + t];
            qa[mt][kj][2] = q0p[8 * kj + t + 4];
            qa[mt][kj][3] = q1p[8 * kj + t + 4];
        }
    }

    float o[2][8][4];
    #pragma unroll
    for (int mt = 0; mt < 2; mt++)
        #pragma unroll
        for (int i = 0; i < 8; i++)
            #pragma unroll
            for (int j = 0; j < 4; j++) o[mt][i][j] = 0.f;
    float mH[2][2], lH[2][2];
    #pragma unroll
    for (int mt = 0; mt < 2; mt++) {
        mH[mt][0] = -INFINITY; mH[mt][1] = -INFINITY;
        lH[mt][0] = 0.f;       lH[mt][1] = 0.f;
    }

    const float SC = 0.125f * 1.4426950408889634f;   // 1/sqrt(64) * log2(e)
    const int ntiles = SS / 64;
    for (int i = 0; i < ntiles; i++) {
        if (i + 1 < ntiles) cp_wait<1>();
        else                cp_wait<0>();
        __syncthreads();
        if (i + 2 < ntiles) load_kv((i + 2) * 64, (i + 2) % NASTAGE);

        const unsigned* kb = (const unsigned*)(k_s + (size_t)(i % NASTAGE) * (KBUF_B / 2));
        const __half*   vb = v_s + (size_t)(i % NASTAGE) * (VBUF_B / 2);
        const unsigned  vb_s = (unsigned)__cvta_generic_to_shared(vb);

        // S = Q @ K^T (fp16 MMA, k-steps of 16)
        float s[2][8][4];
        #pragma unroll
        for (int nt = 0; nt < 8; nt++) {
            #pragma unroll
            for (int mt = 0; mt < 2; mt++)
                s[mt][nt][0] = s[mt][nt][1] = s[mt][nt][2] = s[mt][nt][3] = 0.f;
            const unsigned* krow = &kb[(8 * nt + g) * 36];
            #pragma unroll
            for (int kj = 0; kj < 4; kj++) {
                unsigned b0 = krow[8 * kj + t];
                unsigned b1 = krow[8 * kj + t + 4];
                mma_f16(s[0][nt], qa[0][kj], b0, b1);
                mma_f16(s[1][nt], qa[1][kj], b0, b1);
            }
        }
        // scale to log2 domain (exact fp32)
        #pragma unroll
        for (int mt = 0; mt < 2; mt++)
            #pragma unroll
            for (int nt = 0; nt < 8; nt++)
                #pragma unroll
                for (int j = 0; j < 4; j++) s[mt][nt][j] *= SC;

        // Online softmax per m-group; P packed directly to A-frags
        unsigned pa[2][4][4];
        #pragma unroll
        for (int mt = 0; mt < 2; mt++) {
            float rmax0 = -INFINITY, rmax1 = -INFINITY;
            #pragma unroll
            for (int nt = 0; nt < 8; nt++) {
                rmax0 = fmaxf(rmax0, fmaxf(s[mt][nt][0], s[mt][nt][1]));
                rmax1 = fmaxf(rmax1, fmaxf(s[mt][nt][2], s[mt][nt][3]));
            }
            rmax0 = fmaxf(rmax0, __shfl_xor_sync(FULLMASK, rmax0, 1));
            rmax0 = fmaxf(rmax0, __shfl_xor_sync(FULLMASK, rmax0, 2));
            rmax1 = fmaxf(rmax1, __shfl_xor_sync(FULLMASK, rmax1, 1));
            rmax1 = fmaxf(rmax1, __shfl_xor_sync(FULLMASK, rmax1, 2));

            const float mn0 = fmaxf(mH[mt][0], rmax0);
            const float mn1 = fmaxf(mH[mt][1], rmax1);
            const float cr0 = ex2f(mH[mt][0] - mn0);
            const float cr1 = ex2f(mH[mt][1] - mn1);
            mH[mt][0] = mn0; mH[mt][1] = mn1;
            lH[mt][0] *= cr0; lH[mt][1] *= cr1;
            #pragma unroll
            for (int nt = 0; nt < 8; nt++) {
                o[mt][nt][0] *= cr0; o[mt][nt][1] *= cr0;
                o[mt][nt][2] *= cr1; o[mt][nt][3] *= cr1;
            }

            float ls0 = 0.f, ls1 = 0.f;
            float e[8][4];
            #pragma unroll
            for (int nt = 0; nt < 8; nt++) {
                e[nt][0] = ex2f(s[mt][nt][0] - mn0);
                e[nt][1] = ex2f(s[mt][nt][1] - mn0);
                e[nt][2] = ex2f(s[mt][nt][2] - mn1);
                e[nt][3] = ex2f(s[mt][nt][3] - mn1);
                ls0 += e[nt][0] + e[nt][1];
                ls1 += e[nt][2] + e[nt][3];
            }
            // A-frag packing: a0=(g, cols 2t,2t+1) of tile 2kj; a1=rows+8;
            // a2,a3 same for tile 2kj+1 (k+8). No shuffles.
            #pragma unroll
            for (int kj = 0; kj < 4; kj++) {
                pa[mt][kj][0] = pack2h(e[2 * kj][0],     e[2 * kj][1]);
                pa[mt][kj][1] = pack2h(e[2 * kj][2],     e[2 * kj][3]);
                pa[mt][kj][2] = pack2h(e[2 * kj + 1][0], e[2 * kj + 1][1]);
                pa[mt][kj][3] = pack2h(e[2 * kj + 1][2], e[2 * kj + 1][3]);
            }
            ls0 += __shfl_xor_sync(FULLMASK, ls0, 1);
            ls0 += __shfl_xor_sync(FULLMASK, ls0, 2);
            ls1 += __shfl_xor_sync(FULLMASK, ls1, 1);
            ls1 += __shfl_xor_sync(FULLMASK, ls1, 2);
            lH[mt][0] += ls0; lH[mt][1] += ls1;
        }

        // O += P @ V : V b-frags via ldmatrix.x2.trans
        #pragma unroll
        for (int kj = 0; kj < 4; kj++) {
            unsigned rowa = vb_s + (16 * kj + (lane & 15)) * (KSTRH * 2);
            #pragma unroll
            for (int nd = 0; nd < 8; nd++) {
                unsigned b0, b1;
                ldm_x2_trans(b0, b1, rowa + 16 * nd);
                mma_f16(o[0][nd], pa[0][kj], b0, b1);
                mma_f16(o[1][nd], pa[1][kj], b0, b1);
            }
        }
    }

    // normalize + fp16 store in (B,H,S,HD) layout
    #pragma unroll
    for (int mt = 0; mt < 2; mt++) {
        const float inv0 = 1.f / lH[mt][0];
        const float inv1 = 1.f / lH[mt][1];
        const size_t r0 = (size_t)(b * HH + h) * SS + q0 + w * 32 + mt * 16 + g;
        __half* o0 = out + r0 * HDD;
        __half* o1 = o0 + (size_t)8 * HDD;
        #pragma unroll
        for (int nt = 0; nt < 8; nt++) {
            int col = 8 * nt + 2 * t;
            *(unsigned*)&o0[col] = pack2h(o[mt][nt][0] * inv0,
                                          o[mt][nt][1] * inv0);
            *(unsigned*)&o1[col] = pack2h(o[mt][nt][2] * inv1,
                                          o[mt][nt][3] * inv1);
        }
    }
}

// ---------------------------------------------------------------------------
extern "C" void kernel_launch(void* const* d_in, const int* in_sizes, int n_in,
                              void* d_out, int out_size)
{
    const float* x    = (const float*)d_in[0];
    const float* y    = (const float*)d_in[1];
    const float* W_kv = (const float*)d_in[2];
    const float* b_kv = (const float*)d_in[3];
    const float* W_q  = (const float*)d_in[4];
    const float* b_q  = (const float*)d_in[5];
    const float* W_o  = (const float*)d_in[6];
    const float* b_o  = (const float*)d_in[7];
    float* out = (float*)d_out;

    __half *kvh, *qh, *avh, *xh, *yh;
    unsigned *wkvh, *wqh, *woh;
    cudaGetSymbolAddress((void**)&kvh,  g_kvh);
    cudaGetSymbolAddress((void**)&qh,   g_qh);
    cudaGetSymbolAddress((void**)&avh,  g_avh);
    cudaGetSymbolAddress((void**)&xh,   g_xh);
    cudaGetSymbolAddress((void**)&yh,   g_yh);
    cudaGetSymbolAddress((void**)&wkvh, g_wkvh);
    cudaGetSymbolAddress((void**)&wqh,  g_wqh);
    cudaGetSymbolAddress((void**)&woh,  g_woh);

    cudaFuncSetAttribute(proj_fused_kernel,
        cudaFuncAttributeMaxDynamicSharedMemorySize, GEMM_SMEM);
    cudaFuncSetAttribute(gemm_single_kernel,
        cudaFuncAttributeMaxDynamicSharedMemorySize, GEMM_SMEM);
    cudaFuncSetAttribute(attn_tc_kernel,
        cudaFuncAttributeMaxDynamicSharedMemorySize, ATTN_SMEM);

    // cvt passes
    cvtA_kernel<<<(2 * N4_X + 255) / 256, 256>>>(x, xh, y, yh);
    cvtB_kernel<<<(NW_KV + 2 * NW_W + 255) / 256, 256>>>(
        W_kv, wkvh, W_q, wqh, W_o, woh);

    // Fused kv-proj + q-proj (768 blocks), fp16 outputs
    proj_fused_kernel<<<768, 256, GEMM_SMEM>>>(
        xh, wkvh, b_kv, kvh, yh, wqh, b_q, qh);

    // fused fp16 tensor-core attention -> g_avh ((B,H,S,HD) layout)
    attn_tc_kernel<<<dim3(SS / 256, BB * HH), 256, ATTN_SMEM>>>(
        qh, kvh, avh);

    // out = values @ W_o + b_o [4096 x 1024], fp32 output
    gemm_single_kernel<<<dim3(DD / TBN, MR / TBM), 256, GEMM_SMEM>>>(
        avh, woh, b_o, out, MR, DD, DD);
}